// round 5
// baseline (speedup 1.0000x reference)
#include <cuda_runtime.h>
#include <cuda_fp16.h>
#include <cstdint>

// Problem dims
#define F_OUT 11008   // out features (GEMM M)
#define TOK   8192    // tokens       (GEMM N)
#define KD    4096    // in features  (GEMM K)

// Tiling
#define BM 128
#define BN 256
#define BK 64                 // 128 bytes per row
#define STAGES 4
#define NKITERS (KD / BK)     // 64
#define NUM_M   (F_OUT / BM)  // 86
#define NUM_N   (TOK / BN)    // 32

#define A_STAGE_BYTES (BM * 128)            // 16384
#define B_STAGE_BYTES (BN * 128)            // 32768
#define SLOT_BYTES    (A_STAGE_BYTES + B_STAGE_BYTES)   // 49152
#define SMEM_TOTAL    (STAGES * SLOT_BYTES) // 196608

// Scratch (device globals; allocation-free)
__device__ __align__(256) __half g_wh[(size_t)F_OUT * KD];  // sign(weight) fp16
__device__ __align__(256) __half g_xh[(size_t)TOK * KD];    // x fp16

// ---------------- helpers ----------------
__device__ __forceinline__ uint32_t s2u(const void* p) {
    uint32_t a;
    asm("{ .reg .u64 t; cvta.to.shared.u64 t, %1; cvt.u32.u64 %0, t; }" : "=r"(a) : "l"(p));
    return a;
}
__device__ __forceinline__ void cpasync16(uint32_t saddr, const void* g) {
    asm volatile("cp.async.cg.shared.global [%0], [%1], 16;\n" :: "r"(saddr), "l"(g) : "memory");
}
__device__ __forceinline__ void cp_commit() {
    asm volatile("cp.async.commit_group;\n" ::: "memory");
}
__device__ __forceinline__ void cp_wait2() {
    asm volatile("cp.async.wait_group 2;\n" ::: "memory");
}
__device__ __forceinline__ void cp_wait0() {
    asm volatile("cp.async.wait_group 0;\n" ::: "memory");
}
__device__ __forceinline__ void ldsm_x4(uint32_t* r, uint32_t addr) {
    asm volatile("ldmatrix.sync.aligned.m8n8.x4.shared.b16 {%0,%1,%2,%3}, [%4];"
                 : "=r"(r[0]), "=r"(r[1]), "=r"(r[2]), "=r"(r[3]) : "r"(addr));
}
__device__ __forceinline__ void mma16816(float* d, const uint32_t* a, const uint32_t* b) {
    asm volatile(
        "mma.sync.aligned.m16n8k16.row.col.f32.f16.f16.f32 "
        "{%0,%1,%2,%3}, {%4,%5,%6,%7}, {%8,%9}, {%0,%1,%2,%3};"
        : "+f"(d[0]), "+f"(d[1]), "+f"(d[2]), "+f"(d[3])
        : "r"(a[0]), "r"(a[1]), "r"(a[2]), "r"(a[3]), "r"(b[0]), "r"(b[1]));
}

// ---------------- prep kernels ----------------
__global__ void prep_x_kernel(const float4* __restrict__ x) {
    int i = blockIdx.x * blockDim.x + threadIdx.x;
    const int n4 = TOK * KD / 4;
    if (i < n4) {
        float4 v = x[i];
        __half2* o = reinterpret_cast<__half2*>(g_xh);
        o[2 * i]     = __floats2half2_rn(v.x, v.y);
        o[2 * i + 1] = __floats2half2_rn(v.z, v.w);
    }
}
__global__ void prep_w_kernel(const float4* __restrict__ w) {
    int i = blockIdx.x * blockDim.x + threadIdx.x;
    const int n4 = F_OUT * KD / 4;
    if (i < n4) {
        float4 v = w[i];
        float sx = (v.x > 0.f) ? 1.f : ((v.x < 0.f) ? -1.f : 0.f);
        float sy = (v.y > 0.f) ? 1.f : ((v.y < 0.f) ? -1.f : 0.f);
        float sz = (v.z > 0.f) ? 1.f : ((v.z < 0.f) ? -1.f : 0.f);
        float sw = (v.w > 0.f) ? 1.f : ((v.w < 0.f) ? -1.f : 0.f);
        __half2* o = reinterpret_cast<__half2*>(g_wh);
        o[2 * i]     = __floats2half2_rn(sx, sy);
        o[2 * i + 1] = __floats2half2_rn(sz, sw);
    }
}

// ---------------- GEMM kernel ----------------
// out[token, feature] = W_sign[feature,:] . X[token,:] + bias[feature]
__global__ void __launch_bounds__(512, 1) ternary_gemm_kernel(
    const float* __restrict__ bias, float* __restrict__ out)
{
    extern __shared__ char smem[];
    const uint32_t sb = s2u(smem);
    const int tid = threadIdx.x;
    const int wid = tid >> 5;
    const int lid = tid & 31;

    // grouped rasterization (GROUP_M = 8) for L2 locality
    int pid = blockIdx.x;
    int group   = pid / (8 * NUM_N);
    int first_m = group * 8;
    int gsz     = (NUM_M - first_m < 8) ? (NUM_M - first_m) : 8;
    int pid_m   = first_m + (pid % gsz);
    int pid_n   = (pid % (8 * NUM_N)) / gsz;

    const int f0   = pid_m * BM;   // feature base
    const int tok0 = pid_n * BN;   // token base

    const __half* Ag = g_wh + (size_t)f0 * KD;    // [BM, KD]
    const __half* Bg = g_xh + (size_t)tok0 * KD;  // [BN, KD]

    // ---- cp.async stage fill: rows of 128B, 8x16B chunks, XOR swizzle c^=(r&7)
    auto fill = [&](int s) {
        const uint32_t sbase = sb + (uint32_t)(s & (STAGES - 1)) * SLOT_BYTES;
        const int koff = s * 128;  // bytes along K
        // A: 128 rows x 8 chunks = 1024 ops; 2 per thread, contiguous 32B
        #pragma unroll
        for (int j = 0; j < 2; j++) {
            int idx = tid * 2 + j;
            int r = idx >> 3, c = idx & 7;
            const char* g = (const char*)Ag + (size_t)r * (KD * 2) + koff + c * 16;
            cpasync16(sbase + r * 128 + (((c ^ (r & 7)) << 4)), g);
        }
        // B: 256 rows x 8 chunks = 2048 ops; 4 per thread, contiguous 64B
        #pragma unroll
        for (int j = 0; j < 4; j++) {
            int idx = tid * 4 + j;
            int r = idx >> 3, c = idx & 7;
            const char* g = (const char*)Bg + (size_t)r * (KD * 2) + koff + c * 16;
            cpasync16(sbase + A_STAGE_BYTES + r * 128 + (((c ^ (r & 7)) << 4)), g);
        }
        cp_commit();
    };

    fill(0); fill(1); fill(2);

    // warp tile: 64(M) x 32(N); warp grid 2 x 8
    const int wm = (wid >> 3) * 64;
    const int wn = (wid & 7) * 32;

    float acc[4][4][4];
    #pragma unroll
    for (int mi = 0; mi < 4; mi++)
        #pragma unroll
        for (int ni = 0; ni < 4; ni++)
            #pragma unroll
            for (int k = 0; k < 4; k++) acc[mi][ni][k] = 0.f;

    // precomputed ldmatrix lane terms
    const int a_row_lane = lid & 15;          // A row within 16
    const int a_chi      = (lid >> 4);        // A chunk low bit
    const int b_row_lane = (lid & 7) + ((lid >> 4) << 3);  // B row within 16
    const int b_chi      = (lid >> 3) & 1;    // B chunk low bit

    for (int i = 0; i < NKITERS; i++) {
        cp_wait2();          // stage i resident (positional group semantics)
        __syncthreads();     // also orders: all warps done consuming slot (i+3)&3 at iter i-1

        // issue next stage's loads FIRST so LDGSTS overlaps the MMA work below
        const int s = i + STAGES - 1;
        if (s < NKITERS) fill(s);
        else cp_commit();    // empty group keeps positional accounting uniform

        const uint32_t sa = sb + (uint32_t)(i & (STAGES - 1)) * SLOT_BYTES;
        const uint32_t sbB = sa + A_STAGE_BYTES;

        #pragma unroll
        for (int ks = 0; ks < 4; ks++) {
            uint32_t afr[4][4];
            #pragma unroll
            for (int mi = 0; mi < 4; mi++) {
                int row = wm + mi * 16 + a_row_lane;
                int ch  = ks * 2 + a_chi;
                ldsm_x4(afr[mi], sa + row * 128 + ((ch ^ (row & 7)) << 4));
            }
            uint32_t bfr[2][4];
            #pragma unroll
            for (int p = 0; p < 2; p++) {
                int row = wn + p * 16 + b_row_lane;
                int ch  = ks * 2 + b_chi;
                ldsm_x4(bfr[p], sbB + row * 128 + ((ch ^ (row & 7)) << 4));
            }
            #pragma unroll
            for (int mi = 0; mi < 4; mi++)
                #pragma unroll
                for (int ni = 0; ni < 4; ni++)
                    mma16816(acc[mi][ni], afr[mi], &bfr[ni >> 1][(ni & 1) * 2]);
        }
    }

    cp_wait0();
    __syncthreads();

    // ---- epilogue: transpose through smem -> coalesced stores ----
    // ts[n][m], row stride 132 floats (16B-aligned, conflict-spreading)
    float* ts = reinterpret_cast<float*>(smem);
    {
        const int g = lid >> 2, tq = lid & 3;
        #pragma unroll
        for (int mi = 0; mi < 4; mi++) {
            const int m0 = wm + mi * 16 + g;
            const float b0 = bias[f0 + m0];
            const float b1 = bias[f0 + m0 + 8];
            #pragma unroll
            for (int ni = 0; ni < 4; ni++) {
                const int n0 = wn + ni * 8 + tq * 2;
                ts[(n0)     * 132 + m0]     = acc[mi][ni][0] + b0;
                ts[(n0 + 1) * 132 + m0]     = acc[mi][ni][1] + b0;
                ts[(n0)     * 132 + m0 + 8] = acc[mi][ni][2] + b1;
                ts[(n0 + 1) * 132 + m0 + 8] = acc[mi][ni][3] + b1;
            }
        }
    }
    __syncthreads();
    #pragma unroll
    for (int it = 0; it < (BN * (BM / 4)) / 512; it++) {
        int i = it * 512 + tid;
        int row = i >> 5;          // token row 0..255
        int ch  = i & 31;          // float4 chunk 0..31
        float4 v = *reinterpret_cast<const float4*>(&ts[row * 132 + ch * 4]);
        *reinterpret_cast<float4*>(
            &out[(size_t)(tok0 + row) * F_OUT + f0 + ch * 4]) = v;
    }
}

// ---------------- host ----------------
extern "C" void kernel_launch(void* const* d_in, const int* in_sizes, int n_in,
                              void* d_out, int out_size)
{
    const float* x    = (const float*)d_in[0];
    const float* w    = (const float*)d_in[1];
    const float* bias = (const float*)d_in[2];
    float* out = (float*)d_out;

    prep_x_kernel<<<(TOK * KD / 4) / 256, 256>>>((const float4*)x);
    prep_w_kernel<<<(F_OUT * KD / 4) / 256, 256>>>((const float4*)w);

    cudaFuncSetAttribute(ternary_gemm_kernel,
                         cudaFuncAttributeMaxDynamicSharedMemorySize, SMEM_TOTAL);
    ternary_gemm_kernel<<<NUM_M * NUM_N, 512, SMEM_TOTAL>>>(bias, out);
}

// round 8
// speedup vs baseline: 1.2386x; 1.2386x over previous
#include <cuda_runtime.h>
#include <cuda_fp16.h>
#include <cstdint>

// Problem dims
#define F_OUT 11008   // out features (GEMM M)
#define TOK   8192    // tokens       (GEMM N)
#define KD    4096    // in features  (GEMM K)

// Tiling
#define BM 128
#define BN 256
#define BK 64                 // 128 bytes per row
#define STAGES 4
#define NKITERS (KD / BK)     // 64
#define NUM_M   (F_OUT / BM)  // 86
#define NUM_N   (TOK / BN)    // 32
#define NTHREADS 256          // 8 warps, warp grid 2(M) x 4(N), warp tile 64x64

#define A_STAGE_BYTES (BM * 128)            // 16384
#define B_STAGE_BYTES (BN * 128)            // 32768
#define SLOT_BYTES    (A_STAGE_BYTES + B_STAGE_BYTES)   // 49152
#define SMEM_TOTAL    (STAGES * SLOT_BYTES) // 196608

// Scratch (device globals; allocation-free)
__device__ __align__(256) __half g_wh[(size_t)F_OUT * KD];  // sign(weight) fp16
__device__ __align__(256) __half g_xh[(size_t)TOK * KD];    // x fp16

// ---------------- helpers ----------------
__device__ __forceinline__ uint32_t s2u(const void* p) {
    uint32_t a;
    asm("{ .reg .u64 t; cvta.to.shared.u64 t, %1; cvt.u32.u64 %0, t; }" : "=r"(a) : "l"(p));
    return a;
}
__device__ __forceinline__ void cpasync16(uint32_t saddr, const void* g) {
    asm volatile("cp.async.cg.shared.global [%0], [%1], 16;\n" :: "r"(saddr), "l"(g) : "memory");
}
__device__ __forceinline__ void cp_commit() {
    asm volatile("cp.async.commit_group;\n" ::: "memory");
}
__device__ __forceinline__ void cp_wait2() {
    asm volatile("cp.async.wait_group 2;\n" ::: "memory");
}
__device__ __forceinline__ void cp_wait0() {
    asm volatile("cp.async.wait_group 0;\n" ::: "memory");
}
__device__ __forceinline__ void ldsm_x4(uint32_t* r, uint32_t addr) {
    asm volatile("ldmatrix.sync.aligned.m8n8.x4.shared.b16 {%0,%1,%2,%3}, [%4];"
                 : "=r"(r[0]), "=r"(r[1]), "=r"(r[2]), "=r"(r[3]) : "r"(addr));
}
__device__ __forceinline__ void mma16816(float* d, const uint32_t* a, const uint32_t* b) {
    asm volatile(
        "mma.sync.aligned.m16n8k16.row.col.f32.f16.f16.f32 "
        "{%0,%1,%2,%3}, {%4,%5,%6,%7}, {%8,%9}, {%0,%1,%2,%3};"
        : "+f"(d[0]), "+f"(d[1]), "+f"(d[2]), "+f"(d[3])
        : "r"(a[0]), "r"(a[1]), "r"(a[2]), "r"(a[3]), "r"(b[0]), "r"(b[1]));
}

// ---------------- combined prep kernel ----------------
// region 0: x -> g_xh (fp16), region 1: w -> sign(w) fp16
#define N4X (TOK * KD / 4)
#define N4W (F_OUT * KD / 4)
__global__ void prep_kernel(const float4* __restrict__ x, const float4* __restrict__ w) {
    int i = blockIdx.x * blockDim.x + threadIdx.x;
    if (i < N4X) {
        float4 v = x[i];
        __half2* o = reinterpret_cast<__half2*>(g_xh);
        o[2 * i]     = __floats2half2_rn(v.x, v.y);
        o[2 * i + 1] = __floats2half2_rn(v.z, v.w);
    } else if (i < N4X + N4W) {
        int j = i - N4X;
        float4 v = w[j];
        float sx = (v.x > 0.f) ? 1.f : ((v.x < 0.f) ? -1.f : 0.f);
        float sy = (v.y > 0.f) ? 1.f : ((v.y < 0.f) ? -1.f : 0.f);
        float sz = (v.z > 0.f) ? 1.f : ((v.z < 0.f) ? -1.f : 0.f);
        float sw = (v.w > 0.f) ? 1.f : ((v.w < 0.f) ? -1.f : 0.f);
        __half2* o = reinterpret_cast<__half2*>(g_wh);
        o[2 * j]     = __floats2half2_rn(sx, sy);
        o[2 * j + 1] = __floats2half2_rn(sz, sw);
    }
}

// ---------------- GEMM kernel ----------------
// out[token, feature] = W_sign[feature,:] . X[token,:] + bias[feature]
__global__ void __launch_bounds__(NTHREADS, 1) ternary_gemm_kernel(
    const float* __restrict__ bias, float* __restrict__ out)
{
    extern __shared__ char smem[];
    const uint32_t sb = s2u(smem);
    const int tid = threadIdx.x;
    const int wid = tid >> 5;
    const int lid = tid & 31;

    // grouped rasterization (GROUP_M = 8) for L2 locality
    int pid = blockIdx.x;
    int group   = pid / (8 * NUM_N);
    int first_m = group * 8;
    int gsz     = (NUM_M - first_m < 8) ? (NUM_M - first_m) : 8;
    int pid_m   = first_m + (pid % gsz);
    int pid_n   = (pid % (8 * NUM_N)) / gsz;

    const int f0   = pid_m * BM;   // feature base
    const int tok0 = pid_n * BN;   // token base

    const __half* Ag = g_wh + (size_t)f0 * KD;    // [BM, KD]
    const __half* Bg = g_xh + (size_t)tok0 * KD;  // [BN, KD]

    // ---- cp.async stage fill: rows of 128B, 8x16B chunks, XOR swizzle c^=(r&7)
    // lane-adjacent => chunk-adjacent (coalesced 128B per 8 lanes)
    auto fill = [&](int s) {
        const uint32_t sbase = sb + (uint32_t)(s & (STAGES - 1)) * SLOT_BYTES;
        const int koff = s * 128;  // bytes along K
        // A: 1024 chunks, 4 per thread
        #pragma unroll
        for (int j = 0; j < 4; j++) {
            int idx = j * NTHREADS + tid;
            int r = idx >> 3, c = idx & 7;
            const char* g = (const char*)Ag + (size_t)r * (KD * 2) + koff + c * 16;
            cpasync16(sbase + r * 128 + (((c ^ (r & 7)) << 4)), g);
        }
        // B: 2048 chunks, 8 per thread
        #pragma unroll
        for (int j = 0; j < 8; j++) {
            int idx = j * NTHREADS + tid;
            int r = idx >> 3, c = idx & 7;
            const char* g = (const char*)Bg + (size_t)r * (KD * 2) + koff + c * 16;
            cpasync16(sbase + A_STAGE_BYTES + r * 128 + (((c ^ (r & 7)) << 4)), g);
        }
        cp_commit();
    };

    fill(0); fill(1); fill(2);

    // warp tile: 64(M) x 64(N); warp grid 2 x 4
    const int wm = (wid >> 2) * 64;
    const int wn = (wid & 3) * 64;

    float acc[4][8][4];
    #pragma unroll
    for (int mi = 0; mi < 4; mi++)
        #pragma unroll
        for (int ni = 0; ni < 8; ni++)
            #pragma unroll
            for (int k = 0; k < 4; k++) acc[mi][ni][k] = 0.f;

    // ldmatrix lane terms
    const int a_row_lane = lid & 15;                       // A row within 16
    const int a_chi      = (lid >> 4);                     // A chunk low bit
    const int b_row_lane = (lid & 7) + ((lid >> 4) << 3);  // B row within 16
    const int b_chi      = (lid >> 3) & 1;                 // B chunk low bit

    for (int i = 0; i < NKITERS; i++) {
        cp_wait2();          // stage i resident (positional group semantics)
        __syncthreads();     // all warps done consuming slot (i+3)&3 at iter i-1

        // issue next stage's loads FIRST so LDGSTS overlaps the MMA work below
        const int s = i + STAGES - 1;
        if (s < NKITERS) fill(s);
        else cp_commit();    // empty group keeps positional accounting uniform

        const uint32_t sa = sb + (uint32_t)(i & (STAGES - 1)) * SLOT_BYTES;
        const uint32_t sbB = sa + A_STAGE_BYTES;

        #pragma unroll
        for (int ks = 0; ks < 4; ks++) {
            uint32_t afr[4][4];
            #pragma unroll
            for (int mi = 0; mi < 4; mi++) {
                int row = wm + mi * 16 + a_row_lane;
                int ch  = ks * 2 + a_chi;
                ldsm_x4(afr[mi], sa + row * 128 + ((ch ^ (row & 7)) << 4));
            }
            uint32_t bfr[4][4];
            #pragma unroll
            for (int p = 0; p < 4; p++) {
                int row = wn + p * 16 + b_row_lane;
                int ch  = ks * 2 + b_chi;
                ldsm_x4(bfr[p], sbB + row * 128 + ((ch ^ (row & 7)) << 4));
            }
            #pragma unroll
            for (int mi = 0; mi < 4; mi++)
                #pragma unroll
                for (int ni = 0; ni < 8; ni++)
                    mma16816(acc[mi][ni], afr[mi], &bfr[ni >> 1][(ni & 1) * 2]);
        }
    }

    cp_wait0();
    __syncthreads();

    // ---- epilogue: transpose through smem -> coalesced stores ----
    // ts[n][m], row stride 132 floats (16B-aligned, conflict-spreading)
    float* ts = reinterpret_cast<float*>(smem);
    {
        const int g = lid >> 2, tq = lid & 3;
        #pragma unroll
        for (int mi = 0; mi < 4; mi++) {
            const int m0 = wm + mi * 16 + g;
            const float b0 = bias[f0 + m0];
            const float b1 = bias[f0 + m0 + 8];
            #pragma unroll
            for (int ni = 0; ni < 8; ni++) {
                const int n0 = wn + ni * 8 + tq * 2;
                ts[(n0)     * 132 + m0]     = acc[mi][ni][0] + b0;
                ts[(n0 + 1) * 132 + m0]     = acc[mi][ni][1] + b0;
                ts[(n0)     * 132 + m0 + 8] = acc[mi][ni][2] + b1;
                ts[(n0 + 1) * 132 + m0 + 8] = acc[mi][ni][3] + b1;
            }
        }
    }
    __syncthreads();
    #pragma unroll
    for (int it = 0; it < (BN * (BM / 4)) / NTHREADS; it++) {
        int i = it * NTHREADS + tid;
        int row = i >> 5;          // token row 0..255
        int ch  = i & 31;          // float4 chunk 0..31
        float4 v = *reinterpret_cast<const float4*>(&ts[row * 132 + ch * 4]);
        *reinterpret_cast<float4*>(
            &out[(size_t)(tok0 + row) * F_OUT + f0 + ch * 4]) = v;
    }
}

// ---------------- host ----------------
extern "C" void kernel_launch(void* const* d_in, const int* in_sizes, int n_in,
                              void* d_out, int out_size)
{
    const float* x    = (const float*)d_in[0];
    const float* w    = (const float*)d_in[1];
    const float* bias = (const float*)d_in[2];
    float* out = (float*)d_out;

    prep_kernel<<<(N4X + N4W + 255) / 256, 256>>>((const float4*)x, (const float4*)w);

    cudaFuncSetAttribute(ternary_gemm_kernel,
                         cudaFuncAttributeMaxDynamicSharedMemorySize, SMEM_TOTAL);
    ternary_gemm_kernel<<<NUM_M * NUM_N, NTHREADS, SMEM_TOTAL>>>(bias, out);
}